// round 14
// baseline (speedup 1.0000x reference)
#include <cuda_runtime.h>
#include <cstdint>

// Problem constants
#define T_STEPS 32
#define BATCH   512
#define ACT     64
#define POP     64
#define OUT_DIM 4096   // ACT*POP

#define ROWLEN 92      // padded Wt row (floats); 8 slices at +12-float offsets.
                       // Slice 7 at words [84,92). 368B rows, 16B-aligned;
                       // slice bank quads {0,12,24,4,16,28,8,20} -> LDS.128
                       // conflict-free.
#define WSTRIDE (ROWLEN / 4)   // row stride in ulonglong2 units (23)

#define SBSTR 136      // spike-buffer row stride in BYTES: 64 batches x bf16
                       // + 8B pad; mult of 8 -> LDS.64-aligned reads.

typedef unsigned long long ull;

// Packed fp32x2 ops (Blackwell sm_103a) — single-instruction asm only
#define FMA2(d, a, b, c) \
    asm("fma.rn.f32x2 %0, %1, %2, %3;" : "=l"(d) : "l"(a), "l"(b), "l"(c))
#define ADD2(d, a, b) \
    asm("add.rn.f32x2 %0, %1, %2;" : "=l"(d) : "l"(a), "l"(b))
#define UNPACK2(lo, hi, p) \
    asm("mov.b64 {%0, %1}, %2;" : "=f"(lo), "=f"(hi) : "l"(p))
#define UNPACK2U(lo, hi, p) \
    asm("mov.b64 {%0, %1}, %2;" : "=r"(lo), "=r"(hi) : "l"(p))
#define PACKDUP(d, w) \
    asm("mov.b64 %0, {%1, %1};" : "=l"(d) : "r"(w))

__device__ __forceinline__ void cp_async16(unsigned dst, const void* src) {
    asm volatile("cp.async.cg.shared.global [%0], [%1], 16;"
                 :: "r"(dst), "l"(src) : "memory");
}
__device__ __forceinline__ void cp_commit() {
    asm volatile("cp.async.commit_group;" ::: "memory");
}
__device__ __forceinline__ void cp_wait0() {
    asm volatile("cp.async.wait_group 0;" ::: "memory");
}

__global__ void __launch_bounds__(128, 4)
ilc_snn_kernel(const float* __restrict__ x_seq,   // [T, B, OUT_DIM]
               const float* __restrict__ conn_w,  // [ACT, POP(o), POP(d)]
               const float* __restrict__ conn_b,  // [OUT_DIM]
               float* __restrict__ out)           // [T, B, OUT_DIM]
{
    __shared__ __align__(16) float Wt[64 * ROWLEN];
    // x staging: xs[k*2+j][tid] float4, lane-strided -> conflict-free.
    __shared__ __align__(16) float4 xs[8][128];
    // spike buffer: sb[o][batch] as bf16 (0x3F80 / 0). Row stride 136B.
    // Each warp touches only its own 16-batch columns -> warp-private.
    __shared__ __align__(8) unsigned char sb[64 * SBSTR];

    const int tid   = threadIdx.x;      // 0..127
    const int lane  = tid & 31;
    const int warp  = tid >> 5;         // 0..3
    const int a     = blockIdx.x & 63;  // group
    const int chunk = blockIdx.x >> 6;  // batch chunk (0..7), 64 batches each
    const int slice = lane >> 2;        // o-slice 0..7 (8 outputs each)
    const int blane = lane & 3;
    // 4 CONSECUTIVE batches per thread (so one LDS.64 covers their spikes)
    const int b0    = chunk * 64 + warp * 16 + blane * 4;

    // ---- Load W[a] transposed+padded: Wt[d*92 + 12*(o>>3) + (o&7)] = w[a,o,d] ----
    {
        const float* gw = conn_w + a * 4096;
        #pragma unroll
        for (int i = tid; i < 4096; i += 128) {
            int o = i >> 6;
            int d = i & 63;
            Wt[d * ROWLEN + 12 * (o >> 3) + (o & 7)] = gw[i];
        }
    }
    __syncthreads();   // only block barrier in the kernel

    // ---- Bias for this thread's 8 outputs, straight from global into regs ----
    ull bb[4];
    {
        const ull* gb = (const ull*)(conn_b + a * 64 + slice * 8);
        bb[0] = gb[0]; bb[1] = gb[1]; bb[2] = gb[2]; bb[3] = gb[3];
    }

    // ---- Per-thread state: 4 batches x 8 outputs ----
    float v[4][8];
    ull   fbp[4][4];
    #pragma unroll
    for (int k = 0; k < 4; ++k) {
        #pragma unroll
        for (int o = 0; o < 8; ++o) v[k][o] = 0.0f;
        #pragma unroll
        for (int j = 0; j < 4; ++j) fbp[k][j] = 0ull;   // fb0 = 0 (no bias at t=0)
    }

    const size_t off0 = (size_t)b0 * OUT_DIM + (size_t)a * 64 + (size_t)slice * 8;
    const size_t tstr = (size_t)BATCH * OUT_DIM;
    const float* xp = x_seq + off0;     // source for the *staged* timestep
    float*       op = out   + off0;     // out row for current t

    const ulonglong2* wp = (const ulonglong2*)(Wt + slice * 12);

    // Spike-buffer pointers:
    // write base (this thread, o = slice*8, its 4 batch columns):
    unsigned char* sbw = sb + slice * 8 * SBSTR + (warp * 16 + blane * 4) * 2;
    // read base (d rows, this thread's 4 batch columns):
    const unsigned char* sbr = sb + (warp * 16 + blane * 4) * 2;  // + d*SBSTR

    // Per-thread smem staging address (byte address in shared window)
    const unsigned xs_t =
        (unsigned)__cvta_generic_to_shared(&xs[0][0]) + (unsigned)tid * 16u;

    // Stage x for t = 0 (4 batches x 2 chunks of 16B); slot stride 128*16=2048B
    #pragma unroll
    for (int k = 0; k < 4; ++k) {
        #pragma unroll
        for (int j = 0; j < 2; ++j)
            cp_async16(xs_t + (unsigned)((k * 2 + j) * 2048),
                       xp + (size_t)k * OUT_DIM + j * 4);
    }
    cp_commit();

    for (int t = 0; t < T_STEPS; ++t) {
        cp_wait0();   // x(t) staged

        const bool last = (t + 1 == T_STEPS);

        // ---------- Phase 1: IF update + spike write (global f32 + smem bf16) ----
        #pragma unroll
        for (int k = 0; k < 4; ++k) {
            float4* o4p = (float4*)(op + (size_t)k * OUT_DIM);
            unsigned char* sk = sbw + k * 2;

            #pragma unroll
            for (int j = 0; j < 2; ++j) {
                float4 x = xs[k * 2 + j][tid];
                float f0, f1, f2, f3;
                UNPACK2(f0, f1, fbp[k][2 * j]);
                UNPACK2(f2, f3, fbp[k][2 * j + 1]);

                // v = v + (x_t + fb)   (reference order)
                float v0 = v[k][4 * j + 0] + (x.x + f0);
                float v1 = v[k][4 * j + 1] + (x.y + f1);
                float v2 = v[k][4 * j + 2] + (x.z + f2);
                float v3 = v[k][4 * j + 3] + (x.w + f3);

                bool s0 = (v0 >= 1.0f);
                bool s1 = (v1 >= 1.0f);
                bool s2 = (v2 >= 1.0f);
                bool s3 = (v3 >= 1.0f);

                float4 o4;
                o4.x = s0 ? 1.0f : 0.0f;
                o4.y = s1 ? 1.0f : 0.0f;
                o4.z = s2 ? 1.0f : 0.0f;
                o4.w = s3 ? 1.0f : 0.0f;
                o4p[j] = o4;

                v[k][4 * j + 0] = s0 ? 0.0f : v0;   // hard reset
                v[k][4 * j + 1] = s1 ? 0.0f : v1;
                v[k][4 * j + 2] = s2 ? 0.0f : v2;
                v[k][4 * j + 3] = s3 ? 0.0f : v3;

                // bf16 spike into sb[o][batch] (skip on last step: unused)
                if (!last) {
                    unsigned char* so = sk + (4 * j) * SBSTR;
                    *(unsigned short*)(so + 0 * SBSTR) = s0 ? 0x3F80 : 0;
                    *(unsigned short*)(so + 1 * SBSTR) = s1 ? 0x3F80 : 0;
                    *(unsigned short*)(so + 2 * SBSTR) = s2 ? 0x3F80 : 0;
                    *(unsigned short*)(so + 3 * SBSTR) = s3 ? 0x3F80 : 0;
                }
            }
        }
        op += tstr;

        if (!last) {
            __syncwarp();   // spikes visible to slice-mates (warp-private buffer)

            // ---------- Stage x(t+1) via cp.async (hidden under the matmul) ----
            xp += tstr;
            #pragma unroll
            for (int k = 0; k < 4; ++k) {
                #pragma unroll
                for (int j = 0; j < 2; ++j)
                    cp_async16(xs_t + (unsigned)((k * 2 + j) * 2048),
                               xp + (size_t)k * OUT_DIM + j * 4);
            }
            cp_commit();

            // ---------- Phase 2: fb_new[o] = sum_{d asc} s[d]*Wt[d][o], +bias ----
            #pragma unroll
            for (int k = 0; k < 4; ++k)
                #pragma unroll
                for (int j = 0; j < 4; ++j) fbp[k][j] = 0ull;

            #pragma unroll 8
            for (int d = 0; d < 64; ++d) {
                // spikes of this thread's 4 batches at depth d: one LDS.64
                ull sp = *(const ull*)(sbr + d * SBSTR);
                unsigned lo, hi;
                UNPACK2U(lo, hi, sp);
                // bf16 -> f32 bit pattern: << 16 via PRMT (exact 1.0f / 0.0f)
                unsigned a0 = __byte_perm(lo, 0, 0x1044);
                unsigned a1 = __byte_perm(lo, 0, 0x3244);
                unsigned a2 = __byte_perm(hi, 0, 0x1044);
                unsigned a3 = __byte_perm(hi, 0, 0x3244);
                ull s0, s1, s2, s3;
                PACKDUP(s0, a0);
                PACKDUP(s1, a1);
                PACKDUP(s2, a2);
                PACKDUP(s3, a3);

                const ulonglong2* wr = wp + d * WSTRIDE;
                ulonglong2 wA = wr[0];               // 2x LDS.128, conflict-free
                ulonglong2 wB = wr[1];
                FMA2(fbp[0][0], wA.x, s0, fbp[0][0]);
                FMA2(fbp[0][1], wA.y, s0, fbp[0][1]);
                FMA2(fbp[0][2], wB.x, s0, fbp[0][2]);
                FMA2(fbp[0][3], wB.y, s0, fbp[0][3]);
                FMA2(fbp[1][0], wA.x, s1, fbp[1][0]);
                FMA2(fbp[1][1], wA.y, s1, fbp[1][1]);
                FMA2(fbp[1][2], wB.x, s1, fbp[1][2]);
                FMA2(fbp[1][3], wB.y, s1, fbp[1][3]);
                FMA2(fbp[2][0], wA.x, s2, fbp[2][0]);
                FMA2(fbp[2][1], wA.y, s2, fbp[2][1]);
                FMA2(fbp[2][2], wB.x, s2, fbp[2][2]);
                FMA2(fbp[2][3], wB.y, s2, fbp[2][3]);
                FMA2(fbp[3][0], wA.x, s3, fbp[3][0]);
                FMA2(fbp[3][1], wA.y, s3, fbp[3][1]);
                FMA2(fbp[3][2], wB.x, s3, fbp[3][2]);
                FMA2(fbp[3][3], wB.y, s3, fbp[3][3]);
            }

            // bias after the reduction (reference order), from registers
            #pragma unroll
            for (int k = 0; k < 4; ++k)
                #pragma unroll
                for (int j = 0; j < 4; ++j)
                    ADD2(fbp[k][j], fbp[k][j], bb[j]);

            __syncwarp();   // order this t's spike reads before next t's writes
        }
    }
}

extern "C" void kernel_launch(void* const* d_in, const int* in_sizes, int n_in,
                              void* d_out, int out_size)
{
    const float* x_seq  = (const float*)d_in[0];
    const float* conn_w = (const float*)d_in[1];
    const float* conn_b = (const float*)d_in[2];
    float* out = (float*)d_out;

    // Max smem carveout: 4 CTAs x ~48.2KB = 193KB <= 228KB.
    cudaFuncSetAttribute(ilc_snn_kernel,
                         cudaFuncAttributePreferredSharedMemoryCarveout, 100);

    // 64 groups x 8 batch-chunks of 64; 128 threads = 4 warps x
    // (8 slices x 4 blanes), 4 consecutive batches per thread.
    ilc_snn_kernel<<<512, 128>>>(x_seq, conn_w, conn_b, out);
}

// round 15
// speedup vs baseline: 1.0895x; 1.0895x over previous
#include <cuda_runtime.h>
#include <cstdint>

// Problem constants
#define T_STEPS 32
#define BATCH   512
#define ACT     64
#define POP     64
#define OUT_DIM 4096   // ACT*POP

#define ROWLEN 92      // padded Wt row (floats); 8 slices at +12-float offsets.
                       // Slice 7 occupies words [84,92). 368B rows, 16B-aligned;
                       // slice bank quads {0,12,24,4,16,28,8,20} -> LDS.128
                       // conflict-free.
#define WSTRIDE (ROWLEN / 4)   // row stride in ulonglong2 units (23)

typedef unsigned long long ull;

// Packed fp32x2 ops (Blackwell sm_103a) — single-instruction asm only
#define FMA2(d, a, b, c) \
    asm("fma.rn.f32x2 %0, %1, %2, %3;" : "=l"(d) : "l"(a), "l"(b), "l"(c))
#define ADD2(d, a, b) \
    asm("add.rn.f32x2 %0, %1, %2;" : "=l"(d) : "l"(a), "l"(b))
#define UNPACK2(lo, hi, p) \
    asm("mov.b64 {%0, %1}, %2;" : "=f"(lo), "=f"(hi) : "l"(p))

#define ONES2 0x3f8000003f800000ull

__device__ __forceinline__ void cp_async16(unsigned dst, const void* src) {
    asm volatile("cp.async.cg.shared.global [%0], [%1], 16;"
                 :: "r"(dst), "l"(src) : "memory");
}
__device__ __forceinline__ void cp_commit() {
    asm volatile("cp.async.commit_group;" ::: "memory");
}
__device__ __forceinline__ void cp_wait0() {
    asm volatile("cp.async.wait_group 0;" ::: "memory");
}

__global__ void __launch_bounds__(64, 7)
ilc_snn_kernel(const float* __restrict__ x_seq,   // [T, B, OUT_DIM]
               const float* __restrict__ conn_w,  // [ACT, POP(o), POP(d)]
               const float* __restrict__ conn_b,  // [OUT_DIM]
               float* __restrict__ out)           // [T, B, OUT_DIM]
{
    // Wt[d] row: 92 floats; slice s (o in [8s, 8s+8)) at words [12s, 12s+8).
    __shared__ __align__(16) float Wt[64 * ROWLEN];
    // x staging: xs[k*2+j][tid] is a float4; lane-strided 16B -> conflict-free.
    __shared__ __align__(16) float4 xs[8][64];

    const int tid   = threadIdx.x;      // 0..63
    const int lane  = tid & 31;
    const int warp  = tid >> 5;         // 0..1
    const int a     = blockIdx.x & 63;  // group
    const int chunk = blockIdx.x >> 6;  // batch chunk (0..15), 32 batches each
    const int slice = lane >> 2;        // o-slice 0..7 (8 outputs each)
    const int blane = lane & 3;
    const int b0    = chunk * 32 + warp * 16 + blane;  // batches b0 + {0,4,8,12}

    // ---- Load W[a] transposed+padded: Wt[d*92 + 12*(o>>3) + (o&7)] = w[a,o,d] ----
    {
        const float* gw = conn_w + a * 4096;
        #pragma unroll
        for (int i = tid; i < 4096; i += 64) {
            int o = i >> 6;
            int d = i & 63;
            Wt[d * ROWLEN + 12 * (o >> 3) + (o & 7)] = gw[i];
        }
    }
    __syncthreads();   // only barrier in the kernel

    // ---- Bias for this thread's 8 outputs, straight from global into regs ----
    ull bb[4];
    {
        const ull* gb = (const ull*)(conn_b + a * 64 + slice * 8);
        bb[0] = gb[0]; bb[1] = gb[1]; bb[2] = gb[2]; bb[3] = gb[3];
    }

    // ---- Per-thread state: 4 batches x 8 outputs ----
    float v[4][8];
    ull   fbp[4][4];
    #pragma unroll
    for (int k = 0; k < 4; ++k) {
        #pragma unroll
        for (int o = 0; o < 8; ++o) v[k][o] = 0.0f;
        #pragma unroll
        for (int j = 0; j < 4; ++j) fbp[k][j] = 0ull;   // fb0 = 0 (no bias at t=0)
    }

    const size_t off0 = (size_t)b0 * OUT_DIM + (size_t)a * 64 + (size_t)slice * 8;
    const size_t tstr = (size_t)BATCH * OUT_DIM;
    const float* xp = x_seq + off0;     // source for the *staged* timestep
    float*       op = out   + off0;     // out row for current t

    const ulonglong2* wp = (const ulonglong2*)(Wt + slice * 12);  // row stride WSTRIDE

    // Per-thread smem staging address (byte address in shared window)
    const unsigned xs_t =
        (unsigned)__cvta_generic_to_shared(&xs[0][0]) + (unsigned)tid * 16u;

    // Stage x for t = 0 (4 batches x 2 chunks of 16B); slot stride 64*16 = 1024B
    #pragma unroll
    for (int k = 0; k < 4; ++k) {
        #pragma unroll
        for (int j = 0; j < 2; ++j)
            cp_async16(xs_t + (unsigned)((k * 2 + j) * 1024),
                       xp + (size_t)k * (4 * OUT_DIM) + j * 4);
    }
    cp_commit();

    for (int t = 0; t < T_STEPS; ++t) {
        cp_wait0();   // x(t) staged

        // ---------- Phase 1: IF update + spike write, 4 batches ----------
        unsigned mloc[4];
        #pragma unroll
        for (int k = 0; k < 4; ++k) {
            unsigned m = 0u;
            float4* o4p = (float4*)(op + (size_t)k * (4 * OUT_DIM));

            #pragma unroll
            for (int j = 0; j < 2; ++j) {
                float4 x = xs[k * 2 + j][tid];
                float f0, f1, f2, f3;
                UNPACK2(f0, f1, fbp[k][2 * j]);
                UNPACK2(f2, f3, fbp[k][2 * j + 1]);

                // v = v + (x_t + fb)   (reference order)
                float v0 = v[k][4 * j + 0] + (x.x + f0);
                float v1 = v[k][4 * j + 1] + (x.y + f1);
                float v2 = v[k][4 * j + 2] + (x.z + f2);
                float v3 = v[k][4 * j + 3] + (x.w + f3);

                bool s0 = (v0 >= 1.0f);
                bool s1 = (v1 >= 1.0f);
                bool s2 = (v2 >= 1.0f);
                bool s3 = (v3 >= 1.0f);

                float4 o4;
                o4.x = s0 ? 1.0f : 0.0f;
                o4.y = s1 ? 1.0f : 0.0f;
                o4.z = s2 ? 1.0f : 0.0f;
                o4.w = s3 ? 1.0f : 0.0f;
                o4p[j] = o4;

                v[k][4 * j + 0] = s0 ? 0.0f : v0;   // hard reset
                v[k][4 * j + 1] = s1 ? 0.0f : v1;
                v[k][4 * j + 2] = s2 ? 0.0f : v2;
                v[k][4 * j + 3] = s3 ? 0.0f : v3;

                m |= ((unsigned)s0) << (4 * j + 0);
                m |= ((unsigned)s1) << (4 * j + 1);
                m |= ((unsigned)s2) << (4 * j + 2);
                m |= ((unsigned)s3) << (4 * j + 3);
            }
            mloc[k] = m;
        }
        op += tstr;

        if (t + 1 < T_STEPS) {
            // ---------- Stage x(t+1) via cp.async (no registers, hidden) ----------
            xp += tstr;
            #pragma unroll
            for (int k = 0; k < 4; ++k) {
                #pragma unroll
                for (int j = 0; j < 2; ++j)
                    cp_async16(xs_t + (unsigned)((k * 2 + j) * 1024),
                               xp + (size_t)k * (4 * OUT_DIM) + j * 4);
            }
            cp_commit();

            // ---------- Assemble 64-bit spike masks across the 8 slice-lanes ----
            unsigned mlo[4], mhi[4];
            #pragma unroll
            for (int k = 0; k < 4; ++k) {
                unsigned r = mloc[k] << (8 * (slice & 3));
                r |= __shfl_xor_sync(0xffffffffu, r, 4);
                r |= __shfl_xor_sync(0xffffffffu, r, 8);
                unsigned r2 = __shfl_xor_sync(0xffffffffu, r, 16);
                mlo[k] = (slice < 4) ? r  : r2;     // spike bits d = 0..31
                mhi[k] = (slice < 4) ? r2 : r;      // spike bits d = 32..63
            }

            // ---------- Phase 2: fb_new[o] = sum_{d asc} s[d]*Wt[d][o], +bias ----
            #pragma unroll
            for (int k = 0; k < 4; ++k)
                #pragma unroll
                for (int j = 0; j < 4; ++j) fbp[k][j] = 0ull;

            // Masks consumed 8 bits per block: inner loop fully unrolled so
            // the bit test is an AND-with-IMMEDIATE feeding ISETP (no per-d
            // shifts); one SHR per mask per 8 d. Body ~240 instr -> I$-safe
            // (R13's full-unroll I$ blowup avoided).
            unsigned c0 = mlo[0], c1 = mlo[1], c2 = mlo[2], c3 = mlo[3];
            const ulonglong2* wblk = wp;

            for (int half = 0; half < 2; ++half) {
                for (int blk = 0; blk < 4; ++blk) {
                    #pragma unroll
                    for (int dd = 0; dd < 8; ++dd) {
                        const ulonglong2* wr = wblk + dd * WSTRIDE;
                        ulonglong2 wA = wr[0];       // 2x LDS.128, conflict-free
                        ulonglong2 wB = wr[1];
                        ull s0 = (c0 & (1u << dd)) ? ONES2 : 0ull;
                        ull s1 = (c1 & (1u << dd)) ? ONES2 : 0ull;
                        ull s2 = (c2 & (1u << dd)) ? ONES2 : 0ull;
                        ull s3 = (c3 & (1u << dd)) ? ONES2 : 0ull;
                        FMA2(fbp[0][0], wA.x, s0, fbp[0][0]);
                        FMA2(fbp[0][1], wA.y, s0, fbp[0][1]);
                        FMA2(fbp[0][2], wB.x, s0, fbp[0][2]);
                        FMA2(fbp[0][3], wB.y, s0, fbp[0][3]);
                        FMA2(fbp[1][0], wA.x, s1, fbp[1][0]);
                        FMA2(fbp[1][1], wA.y, s1, fbp[1][1]);
                        FMA2(fbp[1][2], wB.x, s1, fbp[1][2]);
                        FMA2(fbp[1][3], wB.y, s1, fbp[1][3]);
                        FMA2(fbp[2][0], wA.x, s2, fbp[2][0]);
                        FMA2(fbp[2][1], wA.y, s2, fbp[2][1]);
                        FMA2(fbp[2][2], wB.x, s2, fbp[2][2]);
                        FMA2(fbp[2][3], wB.y, s2, fbp[2][3]);
                        FMA2(fbp[3][0], wA.x, s3, fbp[3][0]);
                        FMA2(fbp[3][1], wA.y, s3, fbp[3][1]);
                        FMA2(fbp[3][2], wB.x, s3, fbp[3][2]);
                        FMA2(fbp[3][3], wB.y, s3, fbp[3][3]);
                    }
                    wblk += 8 * WSTRIDE;
                    c0 >>= 8; c1 >>= 8; c2 >>= 8; c3 >>= 8;
                }
                // switch to high-half masks (d = 32..63)
                c0 = mhi[0]; c1 = mhi[1]; c2 = mhi[2]; c3 = mhi[3];
            }

            // bias after the reduction (reference order), from registers
            #pragma unroll
            for (int k = 0; k < 4; ++k)
                #pragma unroll
                for (int j = 0; j < 4; ++j)
                    ADD2(fbp[k][j], fbp[k][j], bb[j]);
        }
    }
}

extern "C" void kernel_launch(void* const* d_in, const int* in_sizes, int n_in,
                              void* d_out, int out_size)
{
    const float* x_seq  = (const float*)d_in[0];
    const float* conn_w = (const float*)d_in[1];
    const float* conn_b = (const float*)d_in[2];
    float* out = (float*)d_out;

    // Keep max smem carveout so smem never caps residency.
    cudaFuncSetAttribute(ilc_snn_kernel,
                         cudaFuncAttributePreferredSharedMemoryCarveout, 100);

    // 64 groups x 16 batch-chunks of 32; 64 threads = 2 warps x (8 slices x 4 blanes).
    ilc_snn_kernel<<<1024, 64>>>(x_seq, conn_w, conn_b, out);
}